// round 1
// baseline (speedup 1.0000x reference)
#include <cuda_runtime.h>
#include <math.h>

#define D 64
#define NMAX 100000
#define EMAX 1600000

// ---------------- scratch (static device memory; no allocs) ----------------
__device__ float    g_hgcn[(size_t)NMAX * D];     // emb @ gcn_W
__device__ float    g_gcn_agg[(size_t)NMAX * D];  // GCN aggregation
__device__ float    g_hgat[(size_t)NMAX * D];     // relu(gcn) @ gat_W
__device__ float    g_gat_agg[(size_t)NMAX * D];  // GAT aggregation
__device__ float    g_gate[(size_t)NMAX * D];
__device__ float    g_hidden[(size_t)NMAX * D];
__device__ float    g_deg[NMAX];
__device__ float    g_dinv[NMAX];
__device__ float    g_as[NMAX];
__device__ float    g_ad[NMAX];
__device__ unsigned g_m[NMAX];                    // encoded segment max
__device__ float    g_z[NMAX];                    // softmax denom
__device__ float    g_edge[EMAX + NMAX];          // per-edge scratch (e, then ex)

// order-preserving float<->uint encoding for atomicMax on floats (incl. negatives)
__device__ __forceinline__ unsigned fenc(float f) {
    unsigned u = __float_as_uint(f);
    return (u & 0x80000000u) ? ~u : (u | 0x80000000u);
}
__device__ __forceinline__ float fdec(unsigned u) {
    return (u & 0x80000000u) ? __uint_as_float(u ^ 0x80000000u)
                             : __uint_as_float(~u);
}
#define ENC_NEG_INF 0x007FFFFFu  // fenc(-inf)

// ---------------- init: zero aggregators, deg=1 (self loop), m=-inf ----------
__global__ void k_init(int n) {
    int i = blockIdx.x * 256 + threadIdx.x;
    if (i < n * D) {
        g_gcn_agg[i] = 0.f;
        g_gat_agg[i] = 0.f;
    }
    if (i < n) {
        g_deg[i] = 1.f;  // self loop pre-counted
        g_z[i]   = 0.f;
        g_m[i]   = ENC_NEG_INF;
    }
}

// ------------- encoder MLP + GCN linear fused: g_hgcn = (relu(ev@W1+b1)@W2+b2)@gcnW
__global__ __launch_bounds__(128) void k_enc(
    const float* __restrict__ ev,
    const float* __restrict__ W1, const float* __restrict__ b1,
    const float* __restrict__ W2, const float* __restrict__ b2,
    const float* __restrict__ Wg, int n)
{
    __shared__ float stage[128 * 65];
    int tid = threadIdx.x;
    int r = blockIdx.x * 128 + tid;
    if (r >= n) return;
    float* st = stage + tid * 65;

    // phase 1: hidden = relu(ev @ W1 + b1)
    float4 e0 = *(const float4*)(ev + (size_t)r * 8);
    float4 e1 = *(const float4*)(ev + (size_t)r * 8 + 4);
    float evv[8] = {e0.x, e0.y, e0.z, e0.w, e1.x, e1.y, e1.z, e1.w};
    float acc[64];
#pragma unroll
    for (int j = 0; j < 64; j += 4) {
        float4 b4 = *(const float4*)(b1 + j);
        acc[j] = b4.x; acc[j + 1] = b4.y; acc[j + 2] = b4.z; acc[j + 3] = b4.w;
    }
#pragma unroll
    for (int k = 0; k < 8; k++) {
        float xk = evv[k];
        const float* w = W1 + k * 64;
#pragma unroll
        for (int j = 0; j < 64; j += 4) {
            float4 w4 = *(const float4*)(w + j);
            acc[j]     += xk * w4.x;
            acc[j + 1] += xk * w4.y;
            acc[j + 2] += xk * w4.z;
            acc[j + 3] += xk * w4.w;
        }
    }
#pragma unroll
    for (int j = 0; j < 64; j++) st[j] = fmaxf(acc[j], 0.f);

    // phase 2: emb = hidden @ W2 + b2
#pragma unroll
    for (int j = 0; j < 64; j += 4) {
        float4 b4 = *(const float4*)(b2 + j);
        acc[j] = b4.x; acc[j + 1] = b4.y; acc[j + 2] = b4.z; acc[j + 3] = b4.w;
    }
    for (int k = 0; k < 64; k++) {
        float xk = st[k];
        const float* w = W2 + k * 64;
#pragma unroll
        for (int j = 0; j < 64; j += 4) {
            float4 w4 = *(const float4*)(w + j);
            acc[j]     += xk * w4.x;
            acc[j + 1] += xk * w4.y;
            acc[j + 2] += xk * w4.z;
            acc[j + 3] += xk * w4.w;
        }
    }
#pragma unroll
    for (int j = 0; j < 64; j++) st[j] = acc[j];

    // phase 3: hgcn = emb @ Wg
#pragma unroll
    for (int j = 0; j < 64; j++) acc[j] = 0.f;
    for (int k = 0; k < 64; k++) {
        float xk = st[k];
        const float* w = Wg + k * 64;
#pragma unroll
        for (int j = 0; j < 64; j += 4) {
            float4 w4 = *(const float4*)(w + j);
            acc[j]     += xk * w4.x;
            acc[j + 1] += xk * w4.y;
            acc[j + 2] += xk * w4.z;
            acc[j + 3] += xk * w4.w;
        }
    }
    float* out = g_hgcn + (size_t)r * 64;
#pragma unroll
    for (int j = 0; j < 64; j += 4)
        *(float4*)(out + j) = make_float4(acc[j], acc[j + 1], acc[j + 2], acc[j + 3]);
}

// ---------------- degree (in-degree on dst) ----------------
__global__ void k_deg(const int* __restrict__ dst, int E) {
    int i = blockIdx.x * 256 + threadIdx.x;
    if (i < E) atomicAdd(&g_deg[dst[i]], 1.f);
}

__global__ void k_dinv(int n) {
    int i = blockIdx.x * 256 + threadIdx.x;
    if (i < n) g_dinv[i] = rsqrtf(g_deg[i]);
}

// ---------------- GCN feature aggregation: 16 threads/edge, float4 each ------
__global__ void k_gcn_agg(const int* __restrict__ src, const int* __restrict__ dst,
                          int E, int n) {
    int t = blockIdx.x * 256 + threadIdx.x;
    int T = (E + n) * 16;
    if (t >= T) return;
    int e = t >> 4;
    int j0 = (t & 15) << 2;
    int s, d;
    if (e < E) { s = src[e]; d = dst[e]; }
    else       { s = e - E;  d = s; }
    float norm = g_dinv[s] * g_dinv[d];
    float4 h = *(const float4*)(g_hgcn + (size_t)s * 64 + j0);
    float* o = g_gcn_agg + (size_t)d * 64 + j0;
    atomicAdd(o + 0, norm * h.x);
    atomicAdd(o + 1, norm * h.y);
    atomicAdd(o + 2, norm * h.z);
    atomicAdd(o + 3, norm * h.w);
}

// -------- GAT linear: h = relu(gcn_agg + gcn_b) @ gat_W; a_s, a_d dots -------
__global__ __launch_bounds__(128) void k_gatlin(
    const float* __restrict__ gcnb, const float* __restrict__ Wg,
    const float* __restrict__ atts, const float* __restrict__ attd, int n)
{
    __shared__ float stage[128 * 65];
    int tid = threadIdx.x;
    int r = blockIdx.x * 128 + tid;
    if (r >= n) return;
    float* st = stage + tid * 65;
    const float* agg = g_gcn_agg + (size_t)r * 64;
#pragma unroll
    for (int j = 0; j < 64; j += 4) {
        float4 a = *(const float4*)(agg + j);
        float4 b = *(const float4*)(gcnb + j);
        st[j]     = fmaxf(a.x + b.x, 0.f);
        st[j + 1] = fmaxf(a.y + b.y, 0.f);
        st[j + 2] = fmaxf(a.z + b.z, 0.f);
        st[j + 3] = fmaxf(a.w + b.w, 0.f);
    }
    float acc[64];
#pragma unroll
    for (int j = 0; j < 64; j++) acc[j] = 0.f;
    for (int k = 0; k < 64; k++) {
        float xk = st[k];
        const float* w = Wg + k * 64;
#pragma unroll
        for (int j = 0; j < 64; j += 4) {
            float4 w4 = *(const float4*)(w + j);
            acc[j]     += xk * w4.x;
            acc[j + 1] += xk * w4.y;
            acc[j + 2] += xk * w4.z;
            acc[j + 3] += xk * w4.w;
        }
    }
    float as = 0.f, ad = 0.f;
    float* out = g_hgat + (size_t)r * 64;
#pragma unroll
    for (int j = 0; j < 64; j += 4) {
        float4 s4 = *(const float4*)(atts + j);
        float4 d4 = *(const float4*)(attd + j);
        as += acc[j] * s4.x + acc[j + 1] * s4.y + acc[j + 2] * s4.z + acc[j + 3] * s4.w;
        ad += acc[j] * d4.x + acc[j + 1] * d4.y + acc[j + 2] * d4.z + acc[j + 3] * d4.w;
        *(float4*)(out + j) = make_float4(acc[j], acc[j + 1], acc[j + 2], acc[j + 3]);
    }
    g_as[r] = as;
    g_ad[r] = ad;
}

// ---------------- GAT edge score + segment max ----------------
__global__ void k_gat_e(const int* __restrict__ src, const int* __restrict__ dst,
                        int E, int n) {
    int i = blockIdx.x * 256 + threadIdx.x;
    if (i >= E + n) return;
    int s, d;
    if (i < E) { s = src[i]; d = dst[i]; }
    else       { s = i - E;  d = s; }
    float e = g_as[s] + g_ad[d];
    e = (e >= 0.f) ? e : 0.2f * e;  // leaky_relu 0.2
    g_edge[i] = e;
    atomicMax(&g_m[d], fenc(e));
}

// ---------------- GAT exp + segment sum ----------------
__global__ void k_gat_sum(const int* __restrict__ dst, int E, int n) {
    int i = blockIdx.x * 256 + threadIdx.x;
    if (i >= E + n) return;
    int d = (i < E) ? dst[i] : (i - E);
    float ex = expf(g_edge[i] - fdec(g_m[d]));
    g_edge[i] = ex;
    atomicAdd(&g_z[d], ex);
}

// ---------------- GAT feature aggregation ----------------
__global__ void k_gat_agg(const int* __restrict__ src, const int* __restrict__ dst,
                          int E, int n) {
    int t = blockIdx.x * 256 + threadIdx.x;
    int T = (E + n) * 16;
    if (t >= T) return;
    int e = t >> 4;
    int j0 = (t & 15) << 2;
    int s, d;
    if (e < E) { s = src[e]; d = dst[e]; }
    else       { s = e - E;  d = s; }
    float alpha = g_edge[e] / g_z[d];
    float4 h = *(const float4*)(g_hgat + (size_t)s * 64 + j0);
    float* o = g_gat_agg + (size_t)d * 64 + j0;
    atomicAdd(o + 0, alpha * h.x);
    atomicAdd(o + 1, alpha * h.y);
    atomicAdd(o + 2, alpha * h.z);
    atomicAdd(o + 3, alpha * h.w);
}

// ----- fusion linear: out = act( [H, relu(gat_agg+gat_b)] @ W[128,64] + b ) --
// ACT=0: sigmoid -> g_gate ; ACT=1: relu -> g_hidden
template <int ACT>
__global__ __launch_bounds__(128) void k_fuse_lin(
    const float* __restrict__ H, const float* __restrict__ W,
    const float* __restrict__ b, const float* __restrict__ gatb, int n)
{
    int r = blockIdx.x * 128 + threadIdx.x;
    if (r >= n) return;
    float acc[64];
#pragma unroll
    for (int j = 0; j < 64; j += 4) {
        float4 b4 = *(const float4*)(b + j);
        acc[j] = b4.x; acc[j + 1] = b4.y; acc[j + 2] = b4.z; acc[j + 3] = b4.w;
    }
    const float* Hr = H + (size_t)r * 64;
    for (int kc = 0; kc < 16; kc++) {
        float4 x4 = *(const float4*)(Hr + kc * 4);
        float xs[4] = {x4.x, x4.y, x4.z, x4.w};
#pragma unroll
        for (int c = 0; c < 4; c++) {
            float xk = xs[c];
            const float* w = W + (kc * 4 + c) * 64;
#pragma unroll
            for (int j = 0; j < 64; j += 4) {
                float4 w4 = *(const float4*)(w + j);
                acc[j]     += xk * w4.x;
                acc[j + 1] += xk * w4.y;
                acc[j + 2] += xk * w4.z;
                acc[j + 3] += xk * w4.w;
            }
        }
    }
    const float* Ar = g_gat_agg + (size_t)r * 64;
    for (int kc = 0; kc < 16; kc++) {
        float4 a4 = *(const float4*)(Ar + kc * 4);
        float4 b4 = *(const float4*)(gatb + kc * 4);
        float xs[4] = {fmaxf(a4.x + b4.x, 0.f), fmaxf(a4.y + b4.y, 0.f),
                       fmaxf(a4.z + b4.z, 0.f), fmaxf(a4.w + b4.w, 0.f)};
#pragma unroll
        for (int c = 0; c < 4; c++) {
            float xk = xs[c];
            const float* w = W + (64 + kc * 4 + c) * 64;
#pragma unroll
            for (int j = 0; j < 64; j += 4) {
                float4 w4 = *(const float4*)(w + j);
                acc[j]     += xk * w4.x;
                acc[j + 1] += xk * w4.y;
                acc[j + 2] += xk * w4.z;
                acc[j + 3] += xk * w4.w;
            }
        }
    }
    float* out = (ACT ? g_hidden : g_gate) + (size_t)r * 64;
#pragma unroll
    for (int j = 0; j < 64; j += 4) {
        float4 v;
        if (ACT) {
            v = make_float4(fmaxf(acc[j], 0.f), fmaxf(acc[j + 1], 0.f),
                            fmaxf(acc[j + 2], 0.f), fmaxf(acc[j + 3], 0.f));
        } else {
            v = make_float4(1.f / (1.f + expf(-acc[j])),
                            1.f / (1.f + expf(-acc[j + 1])),
                            1.f / (1.f + expf(-acc[j + 2])),
                            1.f / (1.f + expf(-acc[j + 3])));
        }
        *(float4*)(out + j) = v;
    }
}

// ---- final: delta = gate*(hidden@res_W2+b2); H_final = H+delta; speed head --
__global__ __launch_bounds__(128) void k_final(
    const float* __restrict__ H,
    const float* __restrict__ rW2, const float* __restrict__ rb2,
    const float* __restrict__ spW1, const float* __restrict__ spb1,
    const float* __restrict__ spW2, const float* __restrict__ spb2,
    float* __restrict__ out_delta, float* __restrict__ out_Hf,
    float* __restrict__ out_pred, int n)
{
    __shared__ float stage[128 * 65];
    int tid = threadIdx.x;
    int r = blockIdx.x * 128 + tid;
    if (r >= n) return;
    float* st = stage + tid * 65;

    float acc[64];
#pragma unroll
    for (int j = 0; j < 64; j += 4) {
        float4 b4 = *(const float4*)(rb2 + j);
        acc[j] = b4.x; acc[j + 1] = b4.y; acc[j + 2] = b4.z; acc[j + 3] = b4.w;
    }
    const float* hid = g_hidden + (size_t)r * 64;
    for (int kc = 0; kc < 16; kc++) {
        float4 x4 = *(const float4*)(hid + kc * 4);
        float xs[4] = {x4.x, x4.y, x4.z, x4.w};
#pragma unroll
        for (int c = 0; c < 4; c++) {
            float xk = xs[c];
            const float* w = rW2 + (kc * 4 + c) * 64;
#pragma unroll
            for (int j = 0; j < 64; j += 4) {
                float4 w4 = *(const float4*)(w + j);
                acc[j]     += xk * w4.x;
                acc[j + 1] += xk * w4.y;
                acc[j + 2] += xk * w4.z;
                acc[j + 3] += xk * w4.w;
            }
        }
    }
    const float* Hr = H + (size_t)r * 64;
    const float* gr = g_gate + (size_t)r * 64;
#pragma unroll
    for (int j = 0; j < 64; j += 4) {
        float4 g4 = *(const float4*)(gr + j);
        float4 h4 = *(const float4*)(Hr + j);
        float4 dd = make_float4(g4.x * acc[j], g4.y * acc[j + 1],
                                g4.z * acc[j + 2], g4.w * acc[j + 3]);
        float4 hf = make_float4(h4.x + dd.x, h4.y + dd.y, h4.z + dd.z, h4.w + dd.w);
        *(float4*)(out_delta + (size_t)r * 64 + j) = dd;
        *(float4*)(out_Hf + (size_t)r * 64 + j) = hf;
        st[j] = hf.x; st[j + 1] = hf.y; st[j + 2] = hf.z; st[j + 3] = hf.w;
    }
    // speed head: pred = relu(Hf @ spW1 + spb1) @ spW2 + spb2
    float sp[32];
#pragma unroll
    for (int t = 0; t < 32; t += 4) {
        float4 b4 = *(const float4*)(spb1 + t);
        sp[t] = b4.x; sp[t + 1] = b4.y; sp[t + 2] = b4.z; sp[t + 3] = b4.w;
    }
    for (int j = 0; j < 64; j++) {
        float hj = st[j];
        const float* w = spW1 + j * 32;
#pragma unroll
        for (int t = 0; t < 32; t += 4) {
            float4 w4 = *(const float4*)(w + t);
            sp[t]     += hj * w4.x;
            sp[t + 1] += hj * w4.y;
            sp[t + 2] += hj * w4.z;
            sp[t + 3] += hj * w4.w;
        }
    }
    float pred = spb2[0];
#pragma unroll
    for (int t = 0; t < 32; t++) pred += fmaxf(sp[t], 0.f) * spW2[t];
    out_pred[r] = pred;
}

// ---------------------------------------------------------------------------
extern "C" void kernel_launch(void* const* d_in, const int* in_sizes, int n_in,
                              void* d_out, int out_size) {
    const float* H    = (const float*)d_in[0];
    const float* ev   = (const float*)d_in[1];
    const int*   ei   = (const int*)d_in[2];
    const float* eW1  = (const float*)d_in[3];
    const float* eb1  = (const float*)d_in[4];
    const float* eW2  = (const float*)d_in[5];
    const float* eb2  = (const float*)d_in[6];
    const float* gcnW = (const float*)d_in[7];
    const float* gcnb = (const float*)d_in[8];
    const float* gatW = (const float*)d_in[9];
    const float* atts = (const float*)d_in[10];
    const float* attd = (const float*)d_in[11];
    const float* gatb = (const float*)d_in[12];
    const float* gateW = (const float*)d_in[13];
    const float* gateb = (const float*)d_in[14];
    const float* rW1  = (const float*)d_in[15];
    const float* rb1  = (const float*)d_in[16];
    const float* rW2  = (const float*)d_in[17];
    const float* rb2  = (const float*)d_in[18];
    const float* spW1 = (const float*)d_in[19];
    const float* spb1 = (const float*)d_in[20];
    const float* spW2 = (const float*)d_in[21];
    const float* spb2 = (const float*)d_in[22];

    int n = in_sizes[0] / D;
    int E = in_sizes[2] / 2;
    const int* src = ei;
    const int* dst = ei + E;
    float* out = (float*)d_out;
    float* out_delta = out;
    float* out_Hf    = out + (size_t)n * D;
    float* out_pred  = out + (size_t)2 * n * D;
    int tEN = E + n;

    k_init<<<(n * D + 255) / 256, 256>>>(n);
    k_enc<<<(n + 127) / 128, 128>>>(ev, eW1, eb1, eW2, eb2, gcnW, n);
    k_deg<<<(E + 255) / 256, 256>>>(dst, E);
    k_dinv<<<(n + 255) / 256, 256>>>(n);
    k_gcn_agg<<<((long long)tEN * 16 + 255) / 256, 256>>>(src, dst, E, n);
    k_gatlin<<<(n + 127) / 128, 128>>>(gcnb, gatW, atts, attd, n);
    k_gat_e<<<(tEN + 255) / 256, 256>>>(src, dst, E, n);
    k_gat_sum<<<(tEN + 255) / 256, 256>>>(dst, E, n);
    k_gat_agg<<<((long long)tEN * 16 + 255) / 256, 256>>>(src, dst, E, n);
    k_fuse_lin<0><<<(n + 127) / 128, 128>>>(H, gateW, gateb, gatb, n);
    k_fuse_lin<1><<<(n + 127) / 128, 128>>>(H, rW1, rb1, gatb, n);
    k_final<<<(n + 127) / 128, 128>>>(H, rW2, rb2, spW1, spb1, spW2, spb2,
                                      out_delta, out_Hf, out_pred, n);
}

// round 2
// speedup vs baseline: 1.2902x; 1.2902x over previous
#include <cuda_runtime.h>
#include <math.h>

#define D 64
#define NMAX 100000
#define EMAX 1600000

// ---------------- scratch (static device memory; no allocs) ----------------
__device__ float g_hgcn[(size_t)NMAX * D];     // emb @ gcn_W
__device__ float g_gcn_agg[(size_t)NMAX * D];  // GCN aggregation (pre-bias)
__device__ float g_hgat[(size_t)NMAX * D];     // relu(gcn) @ gat_W
__device__ float g_gat_agg[(size_t)NMAX * D];  // GAT aggregation (pre-bias)
__device__ float g_gate[(size_t)NMAX * D];
__device__ float g_hidden[(size_t)NMAX * D];
__device__ float g_dinv[NMAX];
__device__ float g_as[NMAX];
__device__ float g_ad[NMAX];
__device__ int   g_cnt[NMAX];      // in-degree (real edges only)
__device__ int   g_cursor[NMAX];   // scatter cursors
__device__ int   g_off[NMAX];      // block-local exclusive scan of cnt
__device__ int   g_bsum[128];      // per-scan-block sums -> exclusive prefix
__device__ int   g_csr[EMAX];      // src node ids grouped by dst

// ---------------- f32x2 packed-FMA helpers ----------------
__device__ __forceinline__ unsigned long long pk2(float x) {
    unsigned long long r; unsigned u = __float_as_uint(x);
    asm("mov.b64 %0, {%1, %1};" : "=l"(r) : "r"(u));
    return r;
}
__device__ __forceinline__ void fma2(unsigned long long& acc,
                                     unsigned long long a, unsigned long long b) {
    asm("fma.rn.f32x2 %0, %1, %2, %3;" : "=l"(acc) : "l"(a), "l"(b), "l"(acc));
}
__device__ __forceinline__ float2 upk(unsigned long long v) {
    float2 f;
    asm("mov.b64 {%0, %1}, %2;" : "=f"(f.x), "=f"(f.y) : "l"(v));
    return f;
}
// acc[32] += xk * W_row[64]   (row 16B-aligned)
__device__ __forceinline__ void fma_row(unsigned long long* acc,
                                        const float* __restrict__ Wrow, float xk) {
    unsigned long long xp = pk2(xk);
    const ulonglong2* row = (const ulonglong2*)Wrow;
#pragma unroll
    for (int j = 0; j < 16; j++) {
        ulonglong2 w = row[j];
        fma2(acc[2 * j],     xp, w.x);
        fma2(acc[2 * j + 1], xp, w.y);
    }
}
// acc[16] += xk * W_row[32]
__device__ __forceinline__ void fma_row32(unsigned long long* acc,
                                          const float* __restrict__ Wrow, float xk) {
    unsigned long long xp = pk2(xk);
    const ulonglong2* row = (const ulonglong2*)Wrow;
#pragma unroll
    for (int j = 0; j < 8; j++) {
        ulonglong2 w = row[j];
        fma2(acc[2 * j],     xp, w.x);
        fma2(acc[2 * j + 1], xp, w.y);
    }
}
__device__ __forceinline__ void load_bias64(unsigned long long* acc,
                                            const float* __restrict__ b) {
    const ulonglong2* b2 = (const ulonglong2*)b;
#pragma unroll
    for (int j = 0; j < 16; j++) {
        ulonglong2 v = b2[j];
        acc[2 * j] = v.x; acc[2 * j + 1] = v.y;
    }
}

// ---------------- init ----------------
__global__ void k_init(int n) {
    int i = blockIdx.x * 256 + threadIdx.x;
    if (i < n) { g_cnt[i] = 0; g_cursor[i] = 0; }
}

// ---------------- in-degree histogram ----------------
__global__ void k_count(const int* __restrict__ dst, int E) {
    int i = blockIdx.x * 256 + threadIdx.x;
    if (i < E) atomicAdd(&g_cnt[dst[i]], 1);
}

// ---------------- 2-level scan (block 1024) ----------------
__global__ void k_scan(int n) {
    __shared__ int sh[1024];
    int t = threadIdx.x;
    int i = blockIdx.x * 1024 + t;
    int v = (i < n) ? g_cnt[i] : 0;
    sh[t] = v;
    __syncthreads();
    for (int o = 1; o < 1024; o <<= 1) {
        int a = (t >= o) ? sh[t - o] : 0;
        __syncthreads();
        sh[t] += a;
        __syncthreads();
    }
    if (i < n) g_off[i] = sh[t] - v;  // block-local exclusive
    if (t == 1023) g_bsum[blockIdx.x] = sh[1023];
}
__global__ void k_scan2(int nb) {
    if (threadIdx.x == 0 && blockIdx.x == 0) {
        int run = 0;
        for (int b = 0; b < nb; b++) { int t = g_bsum[b]; g_bsum[b] = run; run += t; }
    }
}

// ---------------- scatter edges into CSR (grouped by dst) ----------------
__global__ void k_scatter(const int* __restrict__ src, const int* __restrict__ dst, int E) {
    int i = blockIdx.x * 256 + threadIdx.x;
    if (i >= E) return;
    int d = dst[i];
    int pos = atomicAdd(&g_cursor[d], 1);
    g_csr[g_off[d] + g_bsum[d >> 10] + pos] = src[i];
}

__global__ void k_dinv(int n) {
    int i = blockIdx.x * 256 + threadIdx.x;
    if (i < n) g_dinv[i] = rsqrtf((float)(g_cnt[i] + 1));  // +1 self loop
}

// ------------- encoder MLP + GCN linear fused -------------
__global__ __launch_bounds__(128) void k_enc(
    const float* __restrict__ ev,
    const float* __restrict__ W1, const float* __restrict__ b1,
    const float* __restrict__ W2, const float* __restrict__ b2,
    const float* __restrict__ Wg, int n)
{
    __shared__ float stage[128 * 65];
    int tid = threadIdx.x;
    int r = blockIdx.x * 128 + tid;
    if (r >= n) return;
    float* st = stage + tid * 65;

    unsigned long long acc[32];
    // phase 1: hidden = relu(ev @ W1 + b1)
    float4 e0 = *(const float4*)(ev + (size_t)r * 8);
    float4 e1 = *(const float4*)(ev + (size_t)r * 8 + 4);
    load_bias64(acc, b1);
    fma_row(acc, W1 + 0 * 64, e0.x); fma_row(acc, W1 + 1 * 64, e0.y);
    fma_row(acc, W1 + 2 * 64, e0.z); fma_row(acc, W1 + 3 * 64, e0.w);
    fma_row(acc, W1 + 4 * 64, e1.x); fma_row(acc, W1 + 5 * 64, e1.y);
    fma_row(acc, W1 + 6 * 64, e1.z); fma_row(acc, W1 + 7 * 64, e1.w);
#pragma unroll
    for (int i = 0; i < 32; i++) {
        float2 f = upk(acc[i]);
        st[2 * i] = fmaxf(f.x, 0.f); st[2 * i + 1] = fmaxf(f.y, 0.f);
    }
    // phase 2: emb = hidden @ W2 + b2
    load_bias64(acc, b2);
    for (int k = 0; k < 64; k++) fma_row(acc, W2 + k * 64, st[k]);
#pragma unroll
    for (int i = 0; i < 32; i++) {
        float2 f = upk(acc[i]);
        st[2 * i] = f.x; st[2 * i + 1] = f.y;
    }
    // phase 3: hgcn = emb @ gcn_W
#pragma unroll
    for (int i = 0; i < 32; i++) acc[i] = 0ull;
    for (int k = 0; k < 64; k++) fma_row(acc, Wg + k * 64, st[k]);
    float2* out = (float2*)(g_hgcn + (size_t)r * 64);
#pragma unroll
    for (int i = 0; i < 32; i++) out[i] = upk(acc[i]);
}

// ---------------- GCN aggregation: one warp per dst node, no atomics --------
__global__ void k_gcn_agg(int n) {
    int warp = (blockIdx.x * 256 + threadIdx.x) >> 5;
    int lane = threadIdx.x & 31;
    if (warp >= n) return;
    int d = warp;
    int off = g_off[d] + g_bsum[d >> 10];
    int cnt = g_cnt[d];
    float dd = g_dinv[d];
    const float2* hb = (const float2*)g_hgcn;
    float2 self = hb[(size_t)d * 32 + lane];
    float2 acc = make_float2(dd * self.x, dd * self.y);  // self-loop: dinv[d]*h[d]
#pragma unroll 4
    for (int k = 0; k < cnt; k++) {
        int s = g_csr[off + k];
        float w = g_dinv[s];
        float2 h = hb[(size_t)s * 32 + lane];
        acc.x += w * h.x; acc.y += w * h.y;
    }
    acc.x *= dd; acc.y *= dd;
    ((float2*)g_gcn_agg)[(size_t)d * 32 + lane] = acc;
}

// -------- GAT linear: h = relu(gcn_agg + gcn_b) @ gat_W; a_s, a_d dots -------
__global__ __launch_bounds__(128) void k_gatlin(
    const float* __restrict__ gcnb, const float* __restrict__ Wg,
    const float* __restrict__ atts, const float* __restrict__ attd, int n)
{
    __shared__ float stage[128 * 65];
    int tid = threadIdx.x;
    int r = blockIdx.x * 128 + tid;
    if (r >= n) return;
    float* st = stage + tid * 65;
    const float* agg = g_gcn_agg + (size_t)r * 64;
#pragma unroll
    for (int j = 0; j < 64; j += 4) {
        float4 a = *(const float4*)(agg + j);
        float4 b = *(const float4*)(gcnb + j);
        st[j]     = fmaxf(a.x + b.x, 0.f);
        st[j + 1] = fmaxf(a.y + b.y, 0.f);
        st[j + 2] = fmaxf(a.z + b.z, 0.f);
        st[j + 3] = fmaxf(a.w + b.w, 0.f);
    }
    unsigned long long acc[32];
#pragma unroll
    for (int i = 0; i < 32; i++) acc[i] = 0ull;
    for (int k = 0; k < 64; k++) fma_row(acc, Wg + k * 64, st[k]);

    float as = 0.f, ad = 0.f;
    float2* out = (float2*)(g_hgat + (size_t)r * 64);
#pragma unroll
    for (int i = 0; i < 32; i++) {
        float2 f = upk(acc[i]);
        as += f.x * atts[2 * i] + f.y * atts[2 * i + 1];
        ad += f.x * attd[2 * i] + f.y * attd[2 * i + 1];
        out[i] = f;
    }
    g_as[r] = as;
    g_ad[r] = ad;
}

// ---------------- fused GAT: max + exp-sum + weighted aggregate, 1 warp/node
__device__ __forceinline__ float lrelu(float x) {
    return (x >= 0.f) ? x : 0.2f * x;
}
__global__ void k_gat(int n) {
    int warp = (blockIdx.x * 256 + threadIdx.x) >> 5;
    int lane = threadIdx.x & 31;
    if (warp >= n) return;
    int d = warp;
    int off = g_off[d] + g_bsum[d >> 10];
    int cnt = g_cnt[d];
    float a_dd = g_ad[d];
    float e_self = lrelu(g_as[d] + a_dd);

    // pass 1: segment max (lanes parallel over edges)
    float m = e_self;
    for (int k = lane; k < cnt; k += 32) {
        int s = g_csr[off + k];
        m = fmaxf(m, lrelu(g_as[s] + a_dd));
    }
#pragma unroll
    for (int o = 16; o; o >>= 1) m = fmaxf(m, __shfl_xor_sync(0xffffffffu, m, o));

    // pass 2: z = sum exp, acc = sum exp*h (self included); alpha = ex/z factored
    const float2* hb = (const float2*)g_hgat;
    float ex0 = expf(e_self - m);
    float2 hd = hb[(size_t)d * 32 + lane];
    float z = ex0;
    float2 acc = make_float2(ex0 * hd.x, ex0 * hd.y);
#pragma unroll 4
    for (int k = 0; k < cnt; k++) {
        int s = g_csr[off + k];
        float ex = expf(lrelu(g_as[s] + a_dd) - m);
        float2 h = hb[(size_t)s * 32 + lane];
        z += ex;
        acc.x += ex * h.x; acc.y += ex * h.y;
    }
    float inv = 1.f / z;
    ((float2*)g_gat_agg)[(size_t)d * 32 + lane] = make_float2(acc.x * inv, acc.y * inv);
}

// ----- fusion linear: out = act( [H, relu(gat_agg+gat_b)] @ W[128,64] + b ) --
// ACT=0: sigmoid -> g_gate ; ACT=1: relu -> g_hidden
template <int ACT>
__global__ __launch_bounds__(128) void k_fuse_lin(
    const float* __restrict__ H, const float* __restrict__ W,
    const float* __restrict__ b, const float* __restrict__ gatb, int n)
{
    __shared__ float stage[128 * 65];
    int tid = threadIdx.x;
    int r = blockIdx.x * 128 + tid;
    if (r >= n) return;
    float* st = stage + tid * 65;

    unsigned long long acc[32];
    load_bias64(acc, b);
    // half 1: H row
    const float4* Hr = (const float4*)(H + (size_t)r * 64);
#pragma unroll
    for (int j = 0; j < 16; j++) {
        float4 v = Hr[j];
        st[4 * j] = v.x; st[4 * j + 1] = v.y; st[4 * j + 2] = v.z; st[4 * j + 3] = v.w;
    }
    for (int k = 0; k < 64; k++) fma_row(acc, W + k * 64, st[k]);
    // half 2: relu(gat_agg + gat_b)
    const float4* Ar = (const float4*)(g_gat_agg + (size_t)r * 64);
#pragma unroll
    for (int j = 0; j < 16; j++) {
        float4 a = Ar[j];
        float4 bb = *(const float4*)(gatb + 4 * j);
        st[4 * j]     = fmaxf(a.x + bb.x, 0.f);
        st[4 * j + 1] = fmaxf(a.y + bb.y, 0.f);
        st[4 * j + 2] = fmaxf(a.z + bb.z, 0.f);
        st[4 * j + 3] = fmaxf(a.w + bb.w, 0.f);
    }
    for (int k = 0; k < 64; k++) fma_row(acc, W + (64 + k) * 64, st[k]);

    float2* out = (float2*)((ACT ? g_hidden : g_gate) + (size_t)r * 64);
#pragma unroll
    for (int i = 0; i < 32; i++) {
        float2 f = upk(acc[i]);
        if (ACT) {
            out[i] = make_float2(fmaxf(f.x, 0.f), fmaxf(f.y, 0.f));
        } else {
            out[i] = make_float2(1.f / (1.f + expf(-f.x)), 1.f / (1.f + expf(-f.y)));
        }
    }
}

// ---- final: delta = gate*(hidden@res_W2+b2); H_final = H+delta; speed head --
__global__ __launch_bounds__(128) void k_final(
    const float* __restrict__ H,
    const float* __restrict__ rW2, const float* __restrict__ rb2,
    const float* __restrict__ spW1, const float* __restrict__ spb1,
    const float* __restrict__ spW2, const float* __restrict__ spb2,
    float* __restrict__ out_delta, float* __restrict__ out_Hf,
    float* __restrict__ out_pred, int n)
{
    __shared__ float stage[128 * 65];
    int tid = threadIdx.x;
    int r = blockIdx.x * 128 + tid;
    if (r >= n) return;
    float* st = stage + tid * 65;

    unsigned long long acc[32];
    load_bias64(acc, rb2);
    const float4* hid = (const float4*)(g_hidden + (size_t)r * 64);
#pragma unroll
    for (int j = 0; j < 16; j++) {
        float4 v = hid[j];
        st[4 * j] = v.x; st[4 * j + 1] = v.y; st[4 * j + 2] = v.z; st[4 * j + 3] = v.w;
    }
    for (int k = 0; k < 64; k++) fma_row(acc, rW2 + k * 64, st[k]);

    const float2* Hr = (const float2*)(H + (size_t)r * 64);
    const float2* gr = (const float2*)(g_gate + (size_t)r * 64);
    float2* od = (float2*)(out_delta + (size_t)r * 64);
    float2* oh = (float2*)(out_Hf + (size_t)r * 64);
#pragma unroll
    for (int i = 0; i < 32; i++) {
        float2 f = upk(acc[i]);
        float2 g = gr[i];
        float2 h = Hr[i];
        float2 dd = make_float2(g.x * f.x, g.y * f.y);
        float2 hf = make_float2(h.x + dd.x, h.y + dd.y);
        od[i] = dd;
        oh[i] = hf;
        st[2 * i] = hf.x; st[2 * i + 1] = hf.y;
    }
    // speed head: pred = relu(Hf @ spW1 + spb1) @ spW2 + spb2
    unsigned long long sp[16];
    {
        const ulonglong2* b2 = (const ulonglong2*)spb1;
#pragma unroll
        for (int j = 0; j < 8; j++) { ulonglong2 v = b2[j]; sp[2 * j] = v.x; sp[2 * j + 1] = v.y; }
    }
    for (int k = 0; k < 64; k++) fma_row32(sp, spW1 + k * 32, st[k]);
    float pred = spb2[0];
#pragma unroll
    for (int i = 0; i < 16; i++) {
        float2 f = upk(sp[i]);
        pred += fmaxf(f.x, 0.f) * spW2[2 * i] + fmaxf(f.y, 0.f) * spW2[2 * i + 1];
    }
    out_pred[r] = pred;
}

// ---------------------------------------------------------------------------
extern "C" void kernel_launch(void* const* d_in, const int* in_sizes, int n_in,
                              void* d_out, int out_size) {
    const float* H    = (const float*)d_in[0];
    const float* ev   = (const float*)d_in[1];
    const int*   ei   = (const int*)d_in[2];
    const float* eW1  = (const float*)d_in[3];
    const float* eb1  = (const float*)d_in[4];
    const float* eW2  = (const float*)d_in[5];
    const float* eb2  = (const float*)d_in[6];
    const float* gcnW = (const float*)d_in[7];
    const float* gcnb = (const float*)d_in[8];
    const float* gatW = (const float*)d_in[9];
    const float* atts = (const float*)d_in[10];
    const float* attd = (const float*)d_in[11];
    const float* gatb = (const float*)d_in[12];
    const float* gateW = (const float*)d_in[13];
    const float* gateb = (const float*)d_in[14];
    const float* rW1  = (const float*)d_in[15];
    const float* rb1  = (const float*)d_in[16];
    const float* rW2  = (const float*)d_in[17];
    const float* rb2  = (const float*)d_in[18];
    const float* spW1 = (const float*)d_in[19];
    const float* spb1 = (const float*)d_in[20];
    const float* spW2 = (const float*)d_in[21];
    const float* spb2 = (const float*)d_in[22];

    int n = in_sizes[0] / D;
    int E = in_sizes[2] / 2;
    const int* src = ei;
    const int* dst = ei + E;
    float* out = (float*)d_out;
    float* out_delta = out;
    float* out_Hf    = out + (size_t)n * D;
    float* out_pred  = out + (size_t)2 * n * D;
    int nb = (n + 1023) / 1024;

    k_init<<<(n + 255) / 256, 256>>>(n);
    k_count<<<(E + 255) / 256, 256>>>(dst, E);
    k_scan<<<nb, 1024>>>(n);
    k_scan2<<<1, 32>>>(nb);
    k_scatter<<<(E + 255) / 256, 256>>>(src, dst, E);
    k_dinv<<<(n + 255) / 256, 256>>>(n);
    k_enc<<<(n + 127) / 128, 128>>>(ev, eW1, eb1, eW2, eb2, gcnW, n);
    k_gcn_agg<<<(n + 7) / 8, 256>>>(n);
    k_gatlin<<<(n + 127) / 128, 128>>>(gcnb, gatW, atts, attd, n);
    k_gat<<<(n + 7) / 8, 256>>>(n);
    k_fuse_lin<0><<<(n + 127) / 128, 128>>>(H, gateW, gateb, gatb, n);
    k_fuse_lin<1><<<(n + 127) / 128, 128>>>(H, rW1, rb1, gatb, n);
    k_final<<<(n + 127) / 128, 128>>>(H, rW2, rb2, spW1, spb1, spW2, spb2,
                                      out_delta, out_Hf, out_pred, n);
}

// round 3
// speedup vs baseline: 3.7550x; 2.9104x over previous
#include <cuda_runtime.h>
#include <math.h>

#define D 64
#define NMAX 100000
#define EMAX 1600000
typedef unsigned long long ull;

// ---------------- scratch (static device memory; no allocs) ----------------
__device__ float g_hgcn[(size_t)NMAX * D];     // emb @ gcn_W
__device__ float g_gcn_agg[(size_t)NMAX * D];  // GCN aggregation (pre-bias)
__device__ float g_hgat[(size_t)NMAX * D];     // relu(gcn) @ gat_W
__device__ float g_gat_agg[(size_t)NMAX * D];  // GAT aggregation (post-softmax)
__device__ float g_dinv[NMAX];
__device__ float g_as[NMAX];
__device__ float g_ad[NMAX];
__device__ int   g_cnt[NMAX];      // in-degree (real edges only)
__device__ int   g_cursor[NMAX];   // scatter cursors
__device__ int   g_off[NMAX];      // block-local exclusive scan of cnt
__device__ int   g_bsum[128];      // per-scan-block sums -> exclusive prefix
__device__ int   g_csr[EMAX];      // src node ids grouped by dst

// ---------------- f32x2 packed-FMA helpers ----------------
__device__ __forceinline__ ull pk2(float x) {
    ull r; asm("mov.b64 %0, {%1, %1};" : "=l"(r) : "f"(x)); return r;
}
__device__ __forceinline__ ull pkf2(float a, float b) {
    ull r; asm("mov.b64 %0, {%1, %2};" : "=l"(r) : "f"(a), "f"(b)); return r;
}
__device__ __forceinline__ void fma2(ull& acc, ull a, ull b) {
    asm("fma.rn.f32x2 %0, %1, %2, %3;" : "=l"(acc) : "l"(a), "l"(b), "l"(acc));
}
__device__ __forceinline__ float2 upk(ull v) {
    float2 f; asm("mov.b64 {%0, %1}, %2;" : "=f"(f.x), "=f"(f.y) : "l"(v)); return f;
}

// ============ tiled GEMM machinery: block = 128 nodes x 64 cols =============
// threads: 128; tx = tid&7 (cols 8tx..8tx+7), ty = tid>>3 (nodes 8ty..8ty+7)
// xS layout: [node][65] (pad 65 -> conflict-free strided reads)
// acc[i][cp] = packed (y(i, 8tx+2cp), y(i, 8tx+2cp+1))

#define XS_STRIDE 65
#define XS_FLOATS (128 * XS_STRIDE)   // 8320

template <int K>
__device__ __forceinline__ void gemm8x8(const float* __restrict__ xrow,
                                        const float* __restrict__ ws,
                                        int tx, ull acc[8][4])
{
#pragma unroll 8
    for (int k = 0; k < K; k++) {
        ull xp[8];
#pragma unroll
        for (int i = 0; i < 8; i++) xp[i] = pk2(xrow[i * XS_STRIDE + k]);
        const ulonglong2* wp = (const ulonglong2*)(ws + k * 64 + tx * 8);
        ulonglong2 wa = wp[0], wb = wp[1];
#pragma unroll
        for (int i = 0; i < 8; i++) {
            fma2(acc[i][0], xp[i], wa.x);
            fma2(acc[i][1], xp[i], wa.y);
            fma2(acc[i][2], xp[i], wb.x);
            fma2(acc[i][3], xp[i], wb.y);
        }
    }
}

__device__ __forceinline__ void acc_bias(ull acc[8][4], const float* __restrict__ b, int tx) {
    float4 b0 = *(const float4*)(b + tx * 8);
    float4 b1 = *(const float4*)(b + tx * 8 + 4);
    ull p0 = pkf2(b0.x, b0.y), p1 = pkf2(b0.z, b0.w);
    ull p2 = pkf2(b1.x, b1.y), p3 = pkf2(b1.z, b1.w);
#pragma unroll
    for (int i = 0; i < 8; i++) { acc[i][0] = p0; acc[i][1] = p1; acc[i][2] = p2; acc[i][3] = p3; }
}
__device__ __forceinline__ void acc_zero(ull acc[8][4]) {
#pragma unroll
    for (int i = 0; i < 8; i++)
#pragma unroll
        for (int c = 0; c < 4; c++) acc[i][c] = 0ull;
}

// stage 128 node rows (64 floats each) from global into xS; MODE 1: relu(x+bias)
template <int MODE>
__device__ __forceinline__ void stage128(float* xS, const float* __restrict__ src,
                                         const float* __restrict__ bias,
                                         int nodeBase, int n, int tid)
{
#pragma unroll
    for (int r = 0; r < 16; r++) {
        int idx = r * 128 + tid;
        int node = idx >> 4;
        int c4 = (idx & 15) << 2;
        int gn = nodeBase + node;
        float4 v = make_float4(0.f, 0.f, 0.f, 0.f);
        if (gn < n) v = *(const float4*)(src + (size_t)gn * 64 + c4);
        if (MODE == 1) {
            float4 bb = *(const float4*)(bias + c4);
            v.x = fmaxf(v.x + bb.x, 0.f); v.y = fmaxf(v.y + bb.y, 0.f);
            v.z = fmaxf(v.z + bb.z, 0.f); v.w = fmaxf(v.w + bb.w, 0.f);
        }
        float* dst = xS + node * XS_STRIDE + c4;
        dst[0] = v.x; dst[1] = v.y; dst[2] = v.z; dst[3] = v.w;
    }
}

__device__ __forceinline__ void loadW(float* ws, const float* __restrict__ W, int nfloats, int tid) {
    for (int i = tid * 4; i < nfloats; i += 128 * 4)
        *(float4*)(ws + i) = *(const float4*)(W + i);
}

// write acc back into xS (transition between chained GEMMs); RELU optional
template <int RELU>
__device__ __forceinline__ void acc_to_xS(ull acc[8][4], float* xS, int ty, int tx) {
#pragma unroll
    for (int i = 0; i < 8; i++) {
        float* row = xS + (ty * 8 + i) * XS_STRIDE + tx * 8;
#pragma unroll
        for (int cp = 0; cp < 4; cp++) {
            float2 f = upk(acc[i][cp]);
            if (RELU) { f.x = fmaxf(f.x, 0.f); f.y = fmaxf(f.y, 0.f); }
            row[2 * cp] = f.x; row[2 * cp + 1] = f.y;
        }
    }
}

__device__ __forceinline__ void acc_store(ull acc[8][4], float* __restrict__ out,
                                          int nodeBase, int n, int ty, int tx)
{
#pragma unroll
    for (int i = 0; i < 8; i++) {
        int gn = nodeBase + ty * 8 + i;
        if (gn < n) {
            float2 a = upk(acc[i][0]), b = upk(acc[i][1]);
            float2 c = upk(acc[i][2]), d = upk(acc[i][3]);
            *(float4*)(out + (size_t)gn * 64 + tx * 8)     = make_float4(a.x, a.y, b.x, b.y);
            *(float4*)(out + (size_t)gn * 64 + tx * 8 + 4) = make_float4(c.x, c.y, d.x, d.y);
        }
    }
}

// ---------------- CSR build ----------------
__global__ void k_init(int n) {
    int i = blockIdx.x * 256 + threadIdx.x;
    if (i < n) { g_cnt[i] = 0; g_cursor[i] = 0; }
}
__global__ void k_count(const int* __restrict__ dst, int E) {
    int i = blockIdx.x * 256 + threadIdx.x;
    if (i < E) atomicAdd(&g_cnt[dst[i]], 1);
}
__global__ void k_scan(int n) {   // also produces g_dinv
    __shared__ int sh[1024];
    int t = threadIdx.x;
    int i = blockIdx.x * 1024 + t;
    int v = (i < n) ? g_cnt[i] : 0;
    if (i < n) g_dinv[i] = rsqrtf((float)(v + 1));   // +1 self loop
    sh[t] = v;
    __syncthreads();
    for (int o = 1; o < 1024; o <<= 1) {
        int a = (t >= o) ? sh[t - o] : 0;
        __syncthreads();
        sh[t] += a;
        __syncthreads();
    }
    if (i < n) g_off[i] = sh[t] - v;
    if (t == 1023) g_bsum[blockIdx.x] = sh[1023];
}
__global__ void k_scan2(int nb) {
    if (threadIdx.x == 0 && blockIdx.x == 0) {
        int run = 0;
        for (int b = 0; b < nb; b++) { int t = g_bsum[b]; g_bsum[b] = run; run += t; }
    }
}
__global__ void k_scatter(const int* __restrict__ src, const int* __restrict__ dst, int E) {
    int i = blockIdx.x * 256 + threadIdx.x;
    if (i >= E) return;
    int d = dst[i];
    int pos = atomicAdd(&g_cursor[d], 1);
    g_csr[g_off[d] + g_bsum[d >> 10] + pos] = src[i];
}

// ------------- encoder MLP + GCN linear fused (3 chained GEMMs) -------------
extern __shared__ float sm_f[];
__global__ __launch_bounds__(128) void k_enc(
    const float* __restrict__ ev,
    const float* __restrict__ W1, const float* __restrict__ b1,
    const float* __restrict__ W2, const float* __restrict__ b2,
    const float* __restrict__ Wg, int n)
{
    float* xS = sm_f;
    float* ws = sm_f + XS_FLOATS;
    int tid = threadIdx.x, tx = tid & 7, ty = tid >> 3;
    int nb = blockIdx.x * 128;

    // stage ev (128 nodes x 8 feats)
    {
        int gn = nb + tid;
        float4 e0 = make_float4(0, 0, 0, 0), e1 = make_float4(0, 0, 0, 0);
        if (gn < n) {
            e0 = *(const float4*)(ev + (size_t)gn * 8);
            e1 = *(const float4*)(ev + (size_t)gn * 8 + 4);
        }
        float* r = xS + tid * XS_STRIDE;
        r[0] = e0.x; r[1] = e0.y; r[2] = e0.z; r[3] = e0.w;
        r[4] = e1.x; r[5] = e1.y; r[6] = e1.z; r[7] = e1.w;
    }
    loadW(ws, W1, 512, tid);
    __syncthreads();

    ull acc[8][4];
    acc_bias(acc, b1, tx);
    gemm8x8<8>(xS + ty * 8 * XS_STRIDE, ws, tx, acc);
    __syncthreads();
    acc_to_xS<1>(acc, xS, ty, tx);          // relu
    loadW(ws, W2, 4096, tid);
    __syncthreads();

    acc_bias(acc, b2, tx);
    gemm8x8<64>(xS + ty * 8 * XS_STRIDE, ws, tx, acc);
    __syncthreads();
    acc_to_xS<0>(acc, xS, ty, tx);
    loadW(ws, Wg, 4096, tid);
    __syncthreads();

    acc_zero(acc);
    gemm8x8<64>(xS + ty * 8 * XS_STRIDE, ws, tx, acc);
    acc_store(acc, g_hgcn, nb, n, ty, tx);
}

// ---------------- GCN aggregation: one warp per dst node ----------------
__global__ void k_gcn_agg(int n) {
    int warp = (blockIdx.x * 256 + threadIdx.x) >> 5;
    int lane = threadIdx.x & 31;
    if (warp >= n) return;
    int d = warp;
    int off = g_off[d] + g_bsum[d >> 10];
    int cnt = g_cnt[d];
    float dd = g_dinv[d];
    const float2* hb = (const float2*)g_hgcn;
    float2 self = hb[(size_t)d * 32 + lane];
    float2 acc = make_float2(dd * self.x, dd * self.y);
#pragma unroll 4
    for (int k = 0; k < cnt; k++) {
        int s = g_csr[off + k];
        float w = g_dinv[s];
        float2 h = hb[(size_t)s * 32 + lane];
        acc.x += w * h.x; acc.y += w * h.y;
    }
    acc.x *= dd; acc.y *= dd;
    ((float2*)g_gcn_agg)[(size_t)d * 32 + lane] = acc;
}

// ------- GAT linear (tiled): h = relu(gcn_agg+gcnb) @ gatW; as/ad dots ------
__global__ __launch_bounds__(128) void k_gatlin(
    const float* __restrict__ gcnb, const float* __restrict__ gatW,
    const float* __restrict__ atts, const float* __restrict__ attd, int n)
{
    float* xS = sm_f;
    float* ws = sm_f + XS_FLOATS;
    int tid = threadIdx.x, tx = tid & 7, ty = tid >> 3;
    int nb = blockIdx.x * 128;

    stage128<1>(xS, g_gcn_agg, gcnb, nb, n, tid);
    loadW(ws, gatW, 4096, tid);
    __syncthreads();

    ull acc[8][4];
    acc_zero(acc);
    gemm8x8<64>(xS + ty * 8 * XS_STRIDE, ws, tx, acc);

    float4 s0 = *(const float4*)(atts + tx * 8);
    float4 s1 = *(const float4*)(atts + tx * 8 + 4);
    float4 d0 = *(const float4*)(attd + tx * 8);
    float4 d1 = *(const float4*)(attd + tx * 8 + 4);
#pragma unroll
    for (int i = 0; i < 8; i++) {
        int gn = nb + ty * 8 + i;
        float2 a = upk(acc[i][0]), b = upk(acc[i][1]);
        float2 c = upk(acc[i][2]), d = upk(acc[i][3]);
        if (gn < n) {
            *(float4*)(g_hgat + (size_t)gn * 64 + tx * 8)     = make_float4(a.x, a.y, b.x, b.y);
            *(float4*)(g_hgat + (size_t)gn * 64 + tx * 8 + 4) = make_float4(c.x, c.y, d.x, d.y);
        }
        float as = a.x * s0.x + a.y * s0.y + b.x * s0.z + b.y * s0.w
                 + c.x * s1.x + c.y * s1.y + d.x * s1.z + d.y * s1.w;
        float ad = a.x * d0.x + a.y * d0.y + b.x * d0.z + b.y * d0.w
                 + c.x * d1.x + c.y * d1.y + d.x * d1.z + d.y * d1.w;
#pragma unroll
        for (int o = 1; o < 8; o <<= 1) {
            as += __shfl_xor_sync(0xffffffffu, as, o);
            ad += __shfl_xor_sync(0xffffffffu, ad, o);
        }
        if (tx == 0 && gn < n) { g_as[gn] = as; g_ad[gn] = ad; }
    }
}

// ---------------- fused GAT softmax-aggregate: 1 warp/node ----------------
__device__ __forceinline__ float lrelu(float x) { return (x >= 0.f) ? x : 0.2f * x; }
__global__ void k_gat(int n) {
    int warp = (blockIdx.x * 256 + threadIdx.x) >> 5;
    int lane = threadIdx.x & 31;
    if (warp >= n) return;
    int d = warp;
    int off = g_off[d] + g_bsum[d >> 10];
    int cnt = g_cnt[d];
    float a_dd = g_ad[d];
    float e_self = lrelu(g_as[d] + a_dd);

    float m = e_self;
    for (int k = lane; k < cnt; k += 32) {
        int s = g_csr[off + k];
        m = fmaxf(m, lrelu(g_as[s] + a_dd));
    }
#pragma unroll
    for (int o = 16; o; o >>= 1) m = fmaxf(m, __shfl_xor_sync(0xffffffffu, m, o));

    const float2* hb = (const float2*)g_hgat;
    float ex0 = __expf(e_self - m);
    float2 hd = hb[(size_t)d * 32 + lane];
    float z = ex0;
    float2 acc = make_float2(ex0 * hd.x, ex0 * hd.y);
#pragma unroll 4
    for (int k = 0; k < cnt; k++) {
        int s = g_csr[off + k];
        float ex = __expf(lrelu(g_as[s] + a_dd) - m);
        float2 h = hb[(size_t)s * 32 + lane];
        z += ex;
        acc.x += ex * h.x; acc.y += ex * h.y;
    }
    float inv = 1.f / z;
    ((float2*)g_gat_agg)[(size_t)d * 32 + lane] = make_float2(acc.x * inv, acc.y * inv);
}

// --------- fused tail: gate + hidden + delta/Hf + speed head ----------------
__global__ __launch_bounds__(128) void k_fuse(
    const float* __restrict__ H, const float* __restrict__ gatb,
    const float* __restrict__ gateW, const float* __restrict__ gateb,
    const float* __restrict__ rW1, const float* __restrict__ rb1,
    const float* __restrict__ rW2, const float* __restrict__ rb2,
    const float* __restrict__ spW1, const float* __restrict__ spb1,
    const float* __restrict__ spW2, const float* __restrict__ spb2,
    float* __restrict__ out_delta, float* __restrict__ out_Hf,
    float* __restrict__ out_pred, int n)
{
    float* xSa = sm_f;
    float* xSb = sm_f + XS_FLOATS;
    float* ws  = sm_f + 2 * XS_FLOATS;   // 8192 floats
    int tid = threadIdx.x, tx = tid & 7, ty = tid >> 3;
    int nb = blockIdx.x * 128;
    const float* xrowA = xSa + ty * 8 * XS_STRIDE;
    const float* xrowB = xSb + ty * 8 * XS_STRIDE;

    stage128<0>(xSa, H, (const float*)0, nb, n, tid);
    stage128<1>(xSb, g_gat_agg, gatb, nb, n, tid);
    loadW(ws, gateW, 8192, tid);
    __syncthreads();

    // gate = sigmoid([H, diff] @ gateW + gateb) — kept in registers
    ull gacc[8][4];
    acc_bias(gacc, gateb, tx);
    gemm8x8<64>(xrowA, ws, tx, gacc);
    gemm8x8<64>(xrowB, ws + 4096, tx, gacc);
#pragma unroll
    for (int i = 0; i < 8; i++)
#pragma unroll
        for (int cp = 0; cp < 4; cp++) {
            float2 f = upk(gacc[i][cp]);
            f.x = 1.f / (1.f + __expf(-f.x));
            f.y = 1.f / (1.f + __expf(-f.y));
            gacc[i][cp] = pkf2(f.x, f.y);
        }
    __syncthreads();
    loadW(ws, rW1, 8192, tid);
    __syncthreads();

    // hidden = relu([H, diff] @ rW1 + rb1)
    ull acc[8][4];
    acc_bias(acc, rb1, tx);
    gemm8x8<64>(xrowA, ws, tx, acc);
    gemm8x8<64>(xrowB, ws + 4096, tx, acc);
    __syncthreads();
    acc_to_xS<1>(acc, xSa, ty, tx);   // hidden (relu) -> xSa
    loadW(ws, rW2, 4096, tid);
    __syncthreads();

    // raw = hidden @ rW2 + rb2
    acc_bias(acc, rb2, tx);
    gemm8x8<64>(xrowA, ws, tx, acc);

    // epilogue: delta = gate*raw; Hf = H + delta; stage Hf into xSb
#pragma unroll
    for (int i = 0; i < 8; i++) {
        int gn = nb + ty * 8 + i;
        float2 r0 = upk(acc[i][0]), r1 = upk(acc[i][1]);
        float2 r2 = upk(acc[i][2]), r3 = upk(acc[i][3]);
        float2 g0 = upk(gacc[i][0]), g1 = upk(gacc[i][1]);
        float2 g2 = upk(gacc[i][2]), g3 = upk(gacc[i][3]);
        float dv[8] = {g0.x * r0.x, g0.y * r0.y, g1.x * r1.x, g1.y * r1.y,
                       g2.x * r2.x, g2.y * r2.y, g3.x * r3.x, g3.y * r3.y};
        float hf[8];
        if (gn < n) {
            float4 h0 = *(const float4*)(H + (size_t)gn * 64 + tx * 8);
            float4 h1 = *(const float4*)(H + (size_t)gn * 64 + tx * 8 + 4);
            hf[0] = h0.x + dv[0]; hf[1] = h0.y + dv[1];
            hf[2] = h0.z + dv[2]; hf[3] = h0.w + dv[3];
            hf[4] = h1.x + dv[4]; hf[5] = h1.y + dv[5];
            hf[6] = h1.z + dv[6]; hf[7] = h1.w + dv[7];
            *(float4*)(out_delta + (size_t)gn * 64 + tx * 8)     = make_float4(dv[0], dv[1], dv[2], dv[3]);
            *(float4*)(out_delta + (size_t)gn * 64 + tx * 8 + 4) = make_float4(dv[4], dv[5], dv[6], dv[7]);
            *(float4*)(out_Hf + (size_t)gn * 64 + tx * 8)        = make_float4(hf[0], hf[1], hf[2], hf[3]);
            *(float4*)(out_Hf + (size_t)gn * 64 + tx * 8 + 4)    = make_float4(hf[4], hf[5], hf[6], hf[7]);
        } else {
#pragma unroll
            for (int q = 0; q < 8; q++) hf[q] = 0.f;
        }
        float* row = xSb + (ty * 8 + i) * XS_STRIDE + tx * 8;
#pragma unroll
        for (int q = 0; q < 8; q++) row[q] = hf[q];
    }
    __syncthreads();
    loadW(ws, spW1, 2048, tid);   // 64x32
    __syncthreads();

    // speed head: pred = relu(Hf @ spW1 + spb1) @ spW2 + spb2
    // thread tile: 8 nodes (ty) x 4 cols (tx*4)
    ull sacc[8][2];
    {
        float4 sb = *(const float4*)(spb1 + tx * 4);
        ull p0 = pkf2(sb.x, sb.y), p1 = pkf2(sb.z, sb.w);
#pragma unroll
        for (int i = 0; i < 8; i++) { sacc[i][0] = p0; sacc[i][1] = p1; }
    }
#pragma unroll 8
    for (int k = 0; k < 64; k++) {
        ull xp[8];
#pragma unroll
        for (int i = 0; i < 8; i++) xp[i] = pk2(xSb[(ty * 8 + i) * XS_STRIDE + k]);
        ulonglong2 w2 = *(const ulonglong2*)(ws + k * 32 + tx * 4);
#pragma unroll
        for (int i = 0; i < 8; i++) {
            fma2(sacc[i][0], xp[i], w2.x);
            fma2(sacc[i][1], xp[i], w2.y);
        }
    }
    float4 w2v = *(const float4*)(spW2 + tx * 4);
    float sb2 = spb2[0];
#pragma unroll
    for (int i = 0; i < 8; i++) {
        float2 f0 = upk(sacc[i][0]), f1 = upk(sacc[i][1]);
        float p = fmaxf(f0.x, 0.f) * w2v.x + fmaxf(f0.y, 0.f) * w2v.y
                + fmaxf(f1.x, 0.f) * w2v.z + fmaxf(f1.y, 0.f) * w2v.w;
#pragma unroll
        for (int o = 1; o < 8; o <<= 1) p += __shfl_xor_sync(0xffffffffu, p, o);
        int gn = nb + ty * 8 + i;
        if (tx == 0 && gn < n) out_pred[gn] = p + sb2;
    }
}

// ---------------------------------------------------------------------------
extern "C" void kernel_launch(void* const* d_in, const int* in_sizes, int n_in,
                              void* d_out, int out_size) {
    const float* H    = (const float*)d_in[0];
    const float* ev   = (const float*)d_in[1];
    const int*   ei   = (const int*)d_in[2];
    const float* eW1  = (const float*)d_in[3];
    const float* eb1  = (const float*)d_in[4];
    const float* eW2  = (const float*)d_in[5];
    const float* eb2  = (const float*)d_in[6];
    const float* gcnW = (const float*)d_in[7];
    const float* gcnb = (const float*)d_in[8];
    const float* gatW = (const float*)d_in[9];
    const float* atts = (const float*)d_in[10];
    const float* attd = (const float*)d_in[11];
    const float* gatb = (const float*)d_in[12];
    const float* gateW = (const float*)d_in[13];
    const float* gateb = (const float*)d_in[14];
    const float* rW1  = (const float*)d_in[15];
    const float* rb1  = (const float*)d_in[16];
    const float* rW2  = (const float*)d_in[17];
    const float* rb2  = (const float*)d_in[18];
    const float* spW1 = (const float*)d_in[19];
    const float* spb1 = (const float*)d_in[20];
    const float* spW2 = (const float*)d_in[21];
    const float* spb2 = (const float*)d_in[22];

    int n = in_sizes[0] / D;
    int E = in_sizes[2] / 2;
    const int* src = ei;
    const int* dst = ei + E;
    float* out = (float*)d_out;
    float* out_delta = out;
    float* out_Hf    = out + (size_t)n * D;
    float* out_pred  = out + (size_t)2 * n * D;
    int nb1024 = (n + 1023) / 1024;
    int gblk = (n + 127) / 128;

    size_t sm_small = (XS_FLOATS + 4096) * sizeof(float);      // 49,664 B
    size_t sm_fuse  = (2 * XS_FLOATS + 8192) * sizeof(float);  // 99,328 B
    cudaFuncSetAttribute(k_enc,    cudaFuncAttributeMaxDynamicSharedMemorySize, (int)sm_small);
    cudaFuncSetAttribute(k_gatlin, cudaFuncAttributeMaxDynamicSharedMemorySize, (int)sm_small);
    cudaFuncSetAttribute(k_fuse,   cudaFuncAttributeMaxDynamicSharedMemorySize, (int)sm_fuse);

    k_init<<<(n + 255) / 256, 256>>>(n);
    k_count<<<(E + 255) / 256, 256>>>(dst, E);
    k_scan<<<nb1024, 1024>>>(n);
    k_enc<<<gblk, 128, sm_small>>>(ev, eW1, eb1, eW2, eb2, gcnW, n);   // 4th: profiled
    k_scan2<<<1, 32>>>(nb1024);
    k_scatter<<<(E + 255) / 256, 256>>>(src, dst, E);
    k_gcn_agg<<<(n + 7) / 8, 256>>>(n);
    k_gatlin<<<gblk, 128, sm_small>>>(gcnb, gatW, atts, attd, n);
    k_gat<<<(n + 7) / 8, 256>>>(n);
    k_fuse<<<gblk, 128, sm_fuse>>>(H, gatb, gateW, gateb, rW1, rb1, rW2, rb2,
                                   spW1, spb1, spW2, spb2,
                                   out_delta, out_Hf, out_pred, n);
}